// round 17
// baseline (speedup 1.0000x reference)
#include <cuda_runtime.h>
#include <cuda_bf16.h>
#include <cstdint>

#define N 4096
#define D 256
#define NBLK 32            // 4096/128 tiles per dim
#define NSLOT 64           // 32 col-blocks * 2 n-warps
#define TILE_HW (128*72)   // halfwords per smem tile stage (stride 72)
#define MSTR 132           // float stride of staged mask rows (bank-friendly)

__device__ __align__(16) __nv_bfloat16 g_fnb[(size_t)N * D];   // normalized feats bf16 (2 MB)
__device__ float g_part[3][NSLOT][N];                          // partials: S1, P, NEG (3 MB)
__device__ float g_bsum[64];
__device__ unsigned g_cnt = 0;

// ------------------------- PTX helpers -------------------------------------
__device__ __forceinline__ void ldsm_x4(unsigned &r0, unsigned &r1, unsigned &r2, unsigned &r3, unsigned addr) {
    asm volatile("ldmatrix.sync.aligned.m8n8.x4.shared.b16 {%0,%1,%2,%3}, [%4];"
                 : "=r"(r0), "=r"(r1), "=r"(r2), "=r"(r3) : "r"(addr));
}
__device__ __forceinline__ void mma_bf16(float &c0, float &c1, float &c2, float &c3,
                                         unsigned a0, unsigned a1, unsigned a2, unsigned a3,
                                         unsigned b0, unsigned b1) {
    asm volatile("mma.sync.aligned.m16n8k16.row.col.f32.bf16.bf16.f32 "
                 "{%0,%1,%2,%3},{%4,%5,%6,%7},{%8,%9},{%0,%1,%2,%3};"
                 : "+f"(c0), "+f"(c1), "+f"(c2), "+f"(c3)
                 : "r"(a0), "r"(a1), "r"(a2), "r"(a3), "r"(b0), "r"(b1));
}
#define CP16(dst, src) asm volatile("cp.async.cg.shared.global [%0], [%1], 16;" :: "r"(dst), "l"(src))
#define CPCOMMIT()     asm volatile("cp.async.commit_group;")
#define CPWAIT(n)      asm volatile("cp.async.wait_group %0;" :: "n"(n))

// ---------------------------------------------------------------------------
// Kernel B: L2-normalize feature rows -> bf16. 1 warp/row.
// ---------------------------------------------------------------------------
__global__ __launch_bounds__(128) void norm_kernel(const float* __restrict__ f) {
    const int warp = threadIdx.x >> 5;
    const int lane = threadIdx.x & 31;
    const int row  = blockIdx.x * 4 + warp;

    const float4* fr = reinterpret_cast<const float4*>(f + (size_t)row * D) + lane * 2;
    float4 v0 = fr[0];
    float4 v1 = fr[1];

    float s = v0.x*v0.x + v0.y*v0.y + v0.z*v0.z + v0.w*v0.w
            + v1.x*v1.x + v1.y*v1.y + v1.z*v1.z + v1.w*v1.w;
    #pragma unroll
    for (int off = 16; off > 0; off >>= 1)
        s += __shfl_xor_sync(0xffffffffu, s, off);

    const float inv = 1.0f / fmaxf(sqrtf(s), 1e-8f);

    __nv_bfloat162 b0 = __float22bfloat162_rn(make_float2(v0.x*inv, v0.y*inv));
    __nv_bfloat162 b1 = __float22bfloat162_rn(make_float2(v0.z*inv, v0.w*inv));
    __nv_bfloat162 b2 = __float22bfloat162_rn(make_float2(v1.x*inv, v1.y*inv));
    __nv_bfloat162 b3 = __float22bfloat162_rn(make_float2(v1.z*inv, v1.w*inv));

    uint4 u;
    u.x = *reinterpret_cast<unsigned*>(&b0);
    u.y = *reinterpret_cast<unsigned*>(&b1);
    u.z = *reinterpret_cast<unsigned*>(&b2);
    u.w = *reinterpret_cast<unsigned*>(&b3);
    *reinterpret_cast<uint4*>(g_fnb + (size_t)row * D + lane * 8) = u;
}

// ---------------------------------------------------------------------------
// Kernel C: cosim GEMM (bf16 mma.sync, 2-stage cp.async pipeline) + staged
// mask epilogue: after the mainloop, the dead stage smem is reused as two
// 33 KB buffers; pm/nm are streamed tile-chunk-wise via cp.async (deep MLP,
// zero register cost) and consumed from smem via LDS.
// Block 128x128, 8 warps (4M x 2N), warp tile 32x64, K in 4x64.
// ---------------------------------------------------------------------------
extern __shared__ __align__(16) __nv_bfloat16 dynsmem[];

__global__ __launch_bounds__(256, 2) void main_kernel(const float* __restrict__ pm,
                                                      const float* __restrict__ nm) {
    const int tid   = threadIdx.x;
    const int lane  = tid & 31;
    const int warp  = tid >> 5;
    const int warpM = warp >> 1;   // 0..3
    const int warpN = warp & 1;    // 0..1
    const int rowBase = blockIdx.y * 128;
    const int colBase = blockIdx.x * 128;

    float acc[2][8][4];
    #pragma unroll
    for (int i = 0; i < 2; ++i)
        #pragma unroll
        for (int j = 0; j < 8; ++j)
            #pragma unroll
            for (int k = 0; k < 4; ++k) acc[i][j][k] = 0.f;

    // copy mapping: 2 threads per tile-row, 64B (4x16B) each
    const int ldRow = tid >> 1;
    const int ldK   = (tid & 1) * 32;
    const uint4* fA = reinterpret_cast<const uint4*>(g_fnb + (size_t)(rowBase + ldRow) * D) + (ldK >> 3);
    const uint4* fB = reinterpret_cast<const uint4*>(g_fnb + (size_t)(colBase + ldRow) * D) + (ldK >> 3);

    const unsigned sBase = (unsigned)__cvta_generic_to_shared(dynsmem);
    const unsigned sA0 = sBase;                       // stages 0,1
    const unsigned sB0 = sBase + 2 * TILE_HW * 2;     // stages 0,1
    const unsigned dstA = sA0 + (ldRow * 72 + ldK) * 2;
    const unsigned dstB = sB0 + (ldRow * 72 + ldK) * 2;

#define PREFETCH(kb, s) do {                                            \
        unsigned da = dstA + (s) * TILE_HW * 2;                         \
        unsigned db = dstB + (s) * TILE_HW * 2;                         \
        const uint4* pa = fA + (kb) * 8;                                \
        const uint4* pb = fB + (kb) * 8;                                \
        CP16(da +  0, pa + 0); CP16(db +  0, pb + 0);                   \
        CP16(da + 16, pa + 1); CP16(db + 16, pb + 1);                   \
        CP16(da + 32, pa + 2); CP16(db + 32, pb + 2);                   \
        CP16(da + 48, pa + 3); CP16(db + 48, pb + 3);                   \
        CPCOMMIT();                                                     \
    } while (0)

    // ldmatrix per-lane address components
    const int aRow = (lane & 7) + ((lane & 8)  ? 8 : 0);
    const int aK8  = (lane & 16) ? 8 : 0;
    const int bRow = (lane & 7) + ((lane & 16) ? 8 : 0);
    const int bK8  = (lane & 8)  ? 8 : 0;

    PREFETCH(0, 0);
    PREFETCH(1, 1);

    #pragma unroll
    for (int kb = 0; kb < 4; ++kb) {
        if (kb == 3) { CPWAIT(0); } else { CPWAIT(1); }
        __syncthreads();

        const unsigned sA = sA0 + (kb & 1) * TILE_HW * 2;
        const unsigned sB = sB0 + (kb & 1) * TILE_HW * 2;

        #pragma unroll
        for (int kk = 0; kk < 4; ++kk) {
            unsigned b[4][4];
            #pragma unroll
            for (int p = 0; p < 4; ++p) {
                unsigned addr = sB + ((warpN * 64 + p * 16 + bRow) * 72 + kk * 16 + bK8) * 2;
                ldsm_x4(b[p][0], b[p][1], b[p][2], b[p][3], addr);
            }
            unsigned a[2][4];
            #pragma unroll
            for (int mt = 0; mt < 2; ++mt) {
                unsigned addr = sA + ((warpM * 32 + mt * 16 + aRow) * 72 + kk * 16 + aK8) * 2;
                ldsm_x4(a[mt][0], a[mt][1], a[mt][2], a[mt][3], addr);
            }
            #pragma unroll
            for (int mt = 0; mt < 2; ++mt)
                #pragma unroll
                for (int p = 0; p < 4; ++p) {
                    mma_bf16(acc[mt][2*p  ][0], acc[mt][2*p  ][1], acc[mt][2*p  ][2], acc[mt][2*p  ][3],
                             a[mt][0], a[mt][1], a[mt][2], a[mt][3], b[p][0], b[p][1]);
                    mma_bf16(acc[mt][2*p+1][0], acc[mt][2*p+1][1], acc[mt][2*p+1][2], acc[mt][2*p+1][3],
                             a[mt][0], a[mt][1], a[mt][2], a[mt][3], b[p][2], b[p][3]);
                }
        }
        __syncthreads();
        if (kb < 2) {
            if (kb == 0) PREFETCH(2, 0); else PREFETCH(3, 1);
        }
    }
#undef PREFETCH

    // ================= staged mask epilogue =================
    // Buffers: 64 rows x MSTR floats each (33.8 KB); both fit in the dead
    // GEMM stage smem (73.7 KB).
    const float INV_T = 1.0f / 0.07f;
    const int g  = lane >> 2;
    const int t4 = lane & 3;

    float* mb0 = reinterpret_cast<float*>(dynsmem);
    float* mb1 = mb0 + 64 * MSTR;
    const unsigned sb0 = sBase;
    const unsigned sb1 = sBase + 64 * MSTR * 4;

    // stage one 64x128 chunk of a mask into a smem buffer (8 cp.async/thread)
#define STAGE(srcp, rb, sbuf) do {                                          \
        _Pragma("unroll")                                                   \
        for (int c = 0; c < 8; ++c) {                                       \
            const int idx = c * 256 + tid;      /* 0..2047 */               \
            const int row = idx >> 5;                                       \
            const int c16 = idx & 31;                                       \
            const float* sp = (srcp) + (size_t)(rowBase + (rb) + row) * N   \
                              + colBase + c16 * 4;                          \
            CP16((sbuf) + (row * MSTR + c16 * 4) * 4, sp);                  \
        }                                                                   \
        CPCOMMIT();                                                         \
    } while (0)

    float S1[4] = {0.f, 0.f, 0.f, 0.f};
    float P [4] = {0.f, 0.f, 0.f, 0.f};
    float NG[4] = {0.f, 0.f, 0.f, 0.f};

    // consume a pm chunk (rows rb..rb+63): only warps owning those rows work
#define CONSUME_PM(rb, mb) do {                                             \
        if (warpM * 32 >= (rb) && warpM * 32 < (rb) + 64) {                 \
            _Pragma("unroll")                                               \
            for (int mt = 0; mt < 2; ++mt)                                  \
            _Pragma("unroll")                                               \
            for (int hi = 0; hi < 2; ++hi) {                                \
                const int ri = mt * 2 + hi;                                 \
                const int r  = warpM * 32 + mt * 16 + hi * 8 + g;           \
                const int lr = r - (rb);                                    \
                const int grow = rowBase + r;                               \
                _Pragma("unroll")                                           \
                for (int nt = 0; nt < 8; ++nt) {                            \
                    const int col = warpN * 64 + nt * 8 + t4 * 2;           \
                    const int gcol = colBase + col;                         \
                    float2 v = *reinterpret_cast<const float2*>(&(mb)[lr * MSTR + col]); \
                    if (grow == gcol)     v.x = 0.f;                        \
                    if (grow == gcol + 1) v.y = 0.f;                        \
                    const float z0 = acc[mt][nt][hi * 2 + 0] * INV_T;       \
                    const float z1 = acc[mt][nt][hi * 2 + 1] * INV_T;       \
                    S1[ri] += v.x * z0 + v.y * z1;                          \
                    P [ri] += v.x + v.y;                                    \
                }                                                           \
            }                                                               \
        }                                                                   \
    } while (0)

#define CONSUME_NM(rb, mb) do {                                             \
        if (warpM * 32 >= (rb) && warpM * 32 < (rb) + 64) {                 \
            _Pragma("unroll")                                               \
            for (int mt = 0; mt < 2; ++mt)                                  \
            _Pragma("unroll")                                               \
            for (int hi = 0; hi < 2; ++hi) {                                \
                const int ri = mt * 2 + hi;                                 \
                const int r  = warpM * 32 + mt * 16 + hi * 8 + g;           \
                const int lr = r - (rb);                                    \
                const int grow = rowBase + r;                               \
                _Pragma("unroll")                                           \
                for (int nt = 0; nt < 8; ++nt) {                            \
                    const int col = warpN * 64 + nt * 8 + t4 * 2;           \
                    const int gcol = colBase + col;                         \
                    float2 v = *reinterpret_cast<const float2*>(&(mb)[lr * MSTR + col]); \
                    if (grow == gcol)     v.x = 0.f;                        \
                    if (grow == gcol + 1) v.y = 0.f;                        \
                    const float z0 = acc[mt][nt][hi * 2 + 0] * INV_T;       \
                    const float z1 = acc[mt][nt][hi * 2 + 1] * INV_T;       \
                    NG[ri] += v.x * __expf(z0) + v.y * __expf(z1);          \
                }                                                           \
            }                                                               \
        }                                                                   \
    } while (0)

    STAGE(pm, 0, sb0);            // pending: {pm-lo}
    STAGE(pm, 64, sb1);           // pending: {pm-lo, pm-hi}
    CPWAIT(1); __syncthreads();   // pm-lo ready
    CONSUME_PM(0, mb0);           // warps 0-3
    CPWAIT(0); __syncthreads();   // pm-hi ready, buffer0 consumers done
    STAGE(nm, 0, sb0);            // pending: {nm-lo}  (fills while pm-hi consumed)
    CONSUME_PM(64, mb1);          // warps 4-7
    __syncthreads();              // buffer1 consumers done
    STAGE(nm, 64, sb1);           // pending: {nm-lo, nm-hi}
    CPWAIT(1); __syncthreads();   // nm-lo ready
    CONSUME_NM(0, mb0);
    CPWAIT(0); __syncthreads();   // nm-hi ready
    CONSUME_NM(64, mb1);

#undef STAGE
#undef CONSUME_PM
#undef CONSUME_NM

    // reduce across the 4 lanes sharing each row
    #pragma unroll
    for (int ri = 0; ri < 4; ++ri) {
        S1[ri] += __shfl_xor_sync(0xffffffffu, S1[ri], 1);
        S1[ri] += __shfl_xor_sync(0xffffffffu, S1[ri], 2);
        P [ri] += __shfl_xor_sync(0xffffffffu, P [ri], 1);
        P [ri] += __shfl_xor_sync(0xffffffffu, P [ri], 2);
        NG[ri] += __shfl_xor_sync(0xffffffffu, NG[ri], 1);
        NG[ri] += __shfl_xor_sync(0xffffffffu, NG[ri], 2);
    }

    if (t4 == 0) {
        const int cs = blockIdx.x * 2 + warpN;
        #pragma unroll
        for (int ri = 0; ri < 4; ++ri) {
            const int mt = ri >> 1, hi = ri & 1;
            const int grow = rowBase + warpM * 32 + mt * 16 + hi * 8 + g;
            g_part[0][cs][grow] = S1[ri];
            g_part[1][cs][grow] = P[ri];
            g_part[2][cs][grow] = NG[ri];
        }
    }
}

// ---------------------------------------------------------------------------
// Kernel D: per-row finalize + full reduction (last block finishes).
// 64 blocks x 256 threads: 64 rows/block, 4 slot-groups of 16 per row.
// ---------------------------------------------------------------------------
__global__ __launch_bounds__(256) void finalize_kernel(float* __restrict__ out) {
    const int r   = threadIdx.x & 63;          // row within block
    const int p   = threadIdx.x >> 6;          // slot group 0..3
    const int row = blockIdx.x * 64 + r;

    float s1 = 0.f, pp = 0.f, ng = 0.f;
    #pragma unroll
    for (int c = p * 16; c < p * 16 + 16; ++c) {
        s1 += g_part[0][c][row];
        pp += g_part[1][c][row];
        ng += g_part[2][c][row];
    }

    __shared__ float sh[3][4][64];
    sh[0][p][r] = s1; sh[1][p][r] = pp; sh[2][p][r] = ng;
    __syncthreads();

    __shared__ float st[64];
    if (p == 0) {
        s1 = sh[0][0][r] + sh[0][1][r] + sh[0][2][r] + sh[0][3][r];
        pp = sh[1][0][r] + sh[1][1][r] + sh[1][2][r] + sh[1][3][r];
        ng = sh[2][0][r] + sh[2][1][r] + sh[2][2][r] + sh[2][3][r];
        float term = 0.f;
        if (pp > 0.5f) term = (s1 - pp * logf(ng)) / pp;
        st[r] = term;
    }
    __syncthreads();

    __shared__ unsigned s_last;
    if (threadIdx.x < 32) {
        float v = st[threadIdx.x] + st[threadIdx.x + 32];
        #pragma unroll
        for (int off = 16; off > 0; off >>= 1)
            v += __shfl_xor_sync(0xffffffffu, v, off);
        if (threadIdx.x == 0) {
            g_bsum[blockIdx.x] = v;
            __threadfence();
            s_last = atomicAdd(&g_cnt, 1u);
        }
    }
    __syncthreads();

    if (s_last == 63 && threadIdx.x < 32) {
        __threadfence();
        volatile float* vb = g_bsum;
        float v = vb[threadIdx.x] + vb[threadIdx.x + 32];
        #pragma unroll
        for (int off = 16; off > 0; off >>= 1)
            v += __shfl_xor_sync(0xffffffffu, v, off);
        if (threadIdx.x == 0) {
            out[0] = -(v / (float)N);
            g_cnt = 0;   // reset for next graph replay
        }
    }
}

// ---------------------------------------------------------------------------
extern "C" void kernel_launch(void* const* d_in, const int* in_sizes, int n_in,
                              void* d_out, int out_size) {
    (void)in_sizes; (void)n_in; (void)out_size;
    const float* f  = (const float*)d_in[0];
    const float* pm = (const float*)d_in[1];
    const float* nm = (const float*)d_in[2];

    static bool attr_set = false;
    if (!attr_set) {
        cudaFuncSetAttribute(main_kernel, cudaFuncAttributeMaxDynamicSharedMemorySize,
                             4 * TILE_HW * 2);
        attr_set = true;
    }

    norm_kernel<<<N / 4, 128>>>(f);
    dim3 grid(NBLK, NBLK);
    main_kernel<<<grid, 256, 4 * TILE_HW * 2>>>(pm, nm);
    finalize_kernel<<<64, 256>>>((float*)d_out);
}